// round 6
// baseline (speedup 1.0000x reference)
#include <cuda_runtime.h>

// GRUAdder: B = 1048576, T=4, I=2, H=16.
// 8 lanes per batch row: lane q owns gates (2q,2q+1) of r/z/n and h[2q],h[2q+1].
// All weights register-resident (48 packed-f32x2 per lane). h broadcast via
// shfl.idx. 2 rows interleaved per thread, 8 iterations -> 64 rows per warp.

#define TT 4
#define II 2
#define HH 16
#define LROWS 8   // iterations per warp; rows per warp = 8 * LROWS = 64

typedef unsigned long long ull;

__device__ __forceinline__ ull ffma2(ull a, ull b, ull c) {
    ull d;
    asm("fma.rn.f32x2 %0, %1, %2, %3;" : "=l"(d) : "l"(a), "l"(b), "l"(c));
    return d;
}
__device__ __forceinline__ ull pk2(float lo, float hi) {
    ull r;
    asm("mov.b64 %0, {%1, %2};" : "=l"(r) : "f"(lo), "f"(hi));
    return r;
}
__device__ __forceinline__ void upk2(float& lo, float& hi, ull v) {
    asm("mov.b64 {%0, %1}, %2;" : "=f"(lo), "=f"(hi) : "l"(v));
}
__device__ __forceinline__ float fsig(float x) {
    float e, r;
    asm("ex2.approx.f32 %0, %1;" : "=f"(e) : "f"(-1.4426950408889634f * x));
    asm("rcp.approx.f32 %0, %1;" : "=f"(r) : "f"(1.0f + e));
    return r;
}
__device__ __forceinline__ float ftanh_fast(float x) {
    float e, r;
    asm("ex2.approx.f32 %0, %1;" : "=f"(e) : "f"(-2.8853900817779268f * x));
    asm("rcp.approx.f32 %0, %1;" : "=f"(r) : "f"(1.0f + e));
    return 2.0f * r - 1.0f;
}

__global__ void __launch_bounds__(128) gru_adder_kernel(
    const float* __restrict__ x,        // [B, 4, 2]
    const float* __restrict__ w_ih,     // [48, 2]
    const float* __restrict__ w_hh,     // [48, 16]
    const float* __restrict__ b_ih,     // [48]
    const float* __restrict__ b_hh,     // [48]
    const float* __restrict__ w_sum,    // [1, 16]
    const float* __restrict__ b_sum,    // [1]
    const float* __restrict__ w_carry,  // [1, 16]
    const float* __restrict__ b_carry,  // [1]
    float* __restrict__ hid,            // [B, 4, 16]
    float* __restrict__ sumo,           // [B, 4]
    float* __restrict__ carryo,         // [B]
    float* __restrict__ olog,           // [B, 5]
    long long B)
{
    // Pre-paired weights in shared: slot c = cat*8+q (cat: 0=r,1=z,2=n),
    // value = (w[cat*16+2q][k], w[cat*16+2q+1][k]).
    __shared__ __align__(16) ull sh_whh[HH][24];
    __shared__ __align__(16) ull sh_wih[II][24];
    __shared__ __align__(16) ull sh_bR[8], sh_bZ[8], sh_bNi[8], sh_bNh[8];
    __shared__ __align__(16) ull sh_ws[8], sh_wc[8];
    __shared__ float sh_bs, sh_bc;

    const int tidb = threadIdx.x;
    for (int idx = tidb; idx < HH * 24; idx += blockDim.x) {
        int k = idx / 24, c = idx % 24;
        int cat = c >> 3, q = c & 7;
        int j = cat * 16 + 2 * q;
        sh_whh[k][c] = pk2(w_hh[j * HH + k], w_hh[(j + 1) * HH + k]);
    }
    for (int idx = tidb; idx < II * 24; idx += blockDim.x) {
        int i = idx / 24, c = idx % 24;
        int cat = c >> 3, q = c & 7;
        int j = cat * 16 + 2 * q;
        sh_wih[i][c] = pk2(w_ih[j * II + i], w_ih[(j + 1) * II + i]);
    }
    if (tidb < 8) {
        int q = tidb;
        sh_bR[q]  = pk2(b_ih[2*q] + b_hh[2*q],         b_ih[2*q+1] + b_hh[2*q+1]);
        sh_bZ[q]  = pk2(b_ih[16+2*q] + b_hh[16+2*q],   b_ih[17+2*q] + b_hh[17+2*q]);
        sh_bNi[q] = pk2(b_ih[32+2*q],                   b_ih[33+2*q]);
        sh_bNh[q] = pk2(b_hh[32+2*q],                   b_hh[33+2*q]);
        sh_ws[q]  = pk2(w_sum[2*q],   w_sum[2*q+1]);
        sh_wc[q]  = pk2(w_carry[2*q], w_carry[2*q+1]);
        if (q == 0) { sh_bs = b_sum[0]; sh_bc = b_carry[0]; }
    }
    __syncthreads();

    const int lane    = tidb & 31;
    const int q       = lane & 7;       // gate-slice owner within group
    const int grp     = lane >> 3;      // 0..3: which row of the 4 in-flight
    const int grpbase = lane & 24;

    // ---- register-resident weights (one-time shared reads, broadcast) ----
    ull wR[HH], wZ[HH], wN[HH];
    #pragma unroll
    for (int k = 0; k < HH; k++) {
        wR[k] = sh_whh[k][q];
        wZ[k] = sh_whh[k][8 + q];
        wN[k] = sh_whh[k][16 + q];
    }
    const ull uR0 = sh_wih[0][q],      uR1 = sh_wih[1][q];
    const ull uZ0 = sh_wih[0][8 + q],  uZ1 = sh_wih[1][8 + q];
    const ull uN0 = sh_wih[0][16 + q], uN1 = sh_wih[1][16 + q];
    const ull bR = sh_bR[q], bZ = sh_bZ[q], bNi = sh_bNi[q], bNh = sh_bNh[q];
    float wsl, wsh, wcl, wch;
    upk2(wsl, wsh, sh_ws[q]);
    upk2(wcl, wch, sh_wc[q]);
    const float bs = sh_bs, bc = sh_bc;

    const int  warp_global = blockIdx.x * (blockDim.x >> 5) + (tidb >> 5);
    const long long rowbase0 = (long long)warp_global * (8 * LROWS);
    if (rowbase0 >= B) return;

    #pragma unroll 1
    for (int it = 0; it < LROWS; it++) {
        const long long rowA = rowbase0 + it * 8 + grp;
        if (rowA >= B) break;
        const long long rowB = rowA + 4;
        const bool okB = (rowB < B);
        const long long rowBs = okB ? rowB : rowA;   // safe address for loads

        float hA0 = 0.0f, hA1 = 0.0f, hB0 = 0.0f, hB1 = 0.0f;

        #pragma unroll
        for (int t = 0; t < TT; t++) {
            const float2 xA = *reinterpret_cast<const float2*>(x + rowA  * (TT*II) + t*II);
            const float2 xB = *reinterpret_cast<const float2*>(x + rowBs * (TT*II) + t*II);
            const ull xA0 = pk2(xA.x, xA.x), xA1 = pk2(xA.y, xA.y);
            const ull xB0 = pk2(xB.x, xB.x), xB1 = pk2(xB.y, xB.y);

            ull aRA = ffma2(uR1, xA1, ffma2(uR0, xA0, bR));
            ull aZA = ffma2(uZ1, xA1, ffma2(uZ0, xA0, bZ));
            ull gNA = ffma2(uN1, xA1, ffma2(uN0, xA0, bNi));
            ull aNA = bNh;
            ull aRB = ffma2(uR1, xB1, ffma2(uR0, xB0, bR));
            ull aZB = ffma2(uZ1, xB1, ffma2(uZ0, xB0, bZ));
            ull gNB = ffma2(uN1, xB1, ffma2(uN0, xB0, bNi));
            ull aNB = bNh;

            #pragma unroll
            for (int k = 0; k < HH; k++) {
                const int src = grpbase | (k >> 1);
                const float hkA = __shfl_sync(0xffffffffu, (k & 1) ? hA1 : hA0, src);
                const float hkB = __shfl_sync(0xffffffffu, (k & 1) ? hB1 : hB0, src);
                const ull hdA = pk2(hkA, hkA);
                const ull hdB = pk2(hkB, hkB);
                aRA = ffma2(wR[k], hdA, aRA);
                aZA = ffma2(wZ[k], hdA, aZA);
                aNA = ffma2(wN[k], hdA, aNA);
                aRB = ffma2(wR[k], hdB, aRB);
                aZB = ffma2(wZ[k], hdB, aZB);
                aNB = ffma2(wN[k], hdB, aNB);
            }

            // activations + state update (row A)
            {
                float ar0, ar1, az0, az1, an0, an1, gi0, gi1;
                upk2(ar0, ar1, aRA);
                upk2(az0, az1, aZA);
                upk2(an0, an1, aNA);
                upk2(gi0, gi1, gNA);
                float r0 = fsig(ar0), r1 = fsig(ar1);
                float z0 = fsig(az0), z1 = fsig(az1);
                float n0 = ftanh_fast(gi0 + r0 * an0);
                float n1 = ftanh_fast(gi1 + r1 * an1);
                hA0 = n0 + z0 * (hA0 - n0);   // (1-z)*n + z*h
                hA1 = n1 + z1 * (hA1 - n1);
            }
            // activations + state update (row B)
            {
                float ar0, ar1, az0, az1, an0, an1, gi0, gi1;
                upk2(ar0, ar1, aRB);
                upk2(az0, az1, aZB);
                upk2(an0, an1, aNB);
                upk2(gi0, gi1, gNB);
                float r0 = fsig(ar0), r1 = fsig(ar1);
                float z0 = fsig(az0), z1 = fsig(az1);
                float n0 = ftanh_fast(gi0 + r0 * an0);
                float n1 = ftanh_fast(gi1 + r1 * an1);
                hB0 = n0 + z0 * (hB0 - n0);
                hB1 = n1 + z1 * (hB1 - n1);
            }

            // sum head: butterfly all-reduce within 8-lane group
            float spA = hA0 * wsl + hA1 * wsh;
            float spB = hB0 * wsl + hB1 * wsh;
            spA += __shfl_xor_sync(0xffffffffu, spA, 1);
            spA += __shfl_xor_sync(0xffffffffu, spA, 2);
            spA += __shfl_xor_sync(0xffffffffu, spA, 4);
            spB += __shfl_xor_sync(0xffffffffu, spB, 1);
            spB += __shfl_xor_sync(0xffffffffu, spB, 2);
            spB += __shfl_xor_sync(0xffffffffu, spB, 4);
            const float sA = bs + spA;
            const float sB = bs + spB;

            if (hid) {
                *reinterpret_cast<float2*>(hid + rowA * (TT*HH) + t*HH + 2*q) =
                    make_float2(hA0, hA1);
                if (okB)
                    *reinterpret_cast<float2*>(hid + rowB * (TT*HH) + t*HH + 2*q) =
                        make_float2(hB0, hB1);
            }
            if (q == 0) {
                if (sumo) {
                    sumo[rowA * TT + t] = sA;
                    if (okB) sumo[rowB * TT + t] = sB;
                }
            } else if (q == 1) {
                if (olog) {
                    olog[rowA * (TT+1) + t] = sA;
                    if (okB) olog[rowB * (TT+1) + t] = sB;
                }
            }
        }

        // carry head
        float cpA = hA0 * wcl + hA1 * wch;
        float cpB = hB0 * wcl + hB1 * wch;
        cpA += __shfl_xor_sync(0xffffffffu, cpA, 1);
        cpA += __shfl_xor_sync(0xffffffffu, cpA, 2);
        cpA += __shfl_xor_sync(0xffffffffu, cpA, 4);
        cpB += __shfl_xor_sync(0xffffffffu, cpB, 1);
        cpB += __shfl_xor_sync(0xffffffffu, cpB, 2);
        cpB += __shfl_xor_sync(0xffffffffu, cpB, 4);
        const float cA = bc + cpA;
        const float cB = bc + cpB;
        if (q == 2) {
            if (carryo) {
                carryo[rowA] = cA;
                if (okB) carryo[rowB] = cB;
            }
        } else if (q == 3) {
            if (olog) {
                olog[rowA * (TT+1) + TT] = cA;
                if (okB) olog[rowB * (TT+1) + TT] = cB;
            }
        }
    }
}

extern "C" void kernel_launch(void* const* d_in, const int* in_sizes, int n_in,
                              void* d_out, int out_size) {
    const float* x       = (const float*)d_in[0];
    const float* w_ih    = (const float*)d_in[1];
    const float* w_hh    = (const float*)d_in[2];
    const float* b_ih    = (const float*)d_in[3];
    const float* b_hh    = (const float*)d_in[4];
    const float* w_sum   = (const float*)d_in[5];
    const float* b_sum   = (const float*)d_in[6];
    const float* w_carry = (const float*)d_in[7];
    const float* b_carry = (const float*)d_in[8];

    long long B = (long long)in_sizes[0] / (TT * II);
    float* out = (float*)d_out;
    long long os = (long long)out_size;

    // Output layout: concatenation of flattened (hidden_table, sum_logits,
    // carry_logit, output_logits) = 74 floats per row; fall back otherwise.
    float *hid = nullptr, *sum = nullptr, *car = nullptr, *olog = nullptr;
    if (os >= B * 74) {
        hid = out; sum = out + B * 64; car = out + B * 68; olog = out + B * 69;
    } else if (os >= B * 64) {
        hid = out;
    } else if (os >= B * 5) {
        olog = out;
    } else if (os >= B * 4) {
        sum = out;
    } else {
        car = out;
    }

    const int threads = 128;                       // 4 warps per CTA
    const long long rows_per_warp = 8 * LROWS;     // 64
    long long warps = (B + rows_per_warp - 1) / rows_per_warp;
    long long ctas  = (warps + 3) / 4;
    gru_adder_kernel<<<(int)ctas, threads>>>(x, w_ih, w_hh, b_ih, b_hh,
                                             w_sum, b_sum, w_carry, b_carry,
                                             hid, sum, car, olog, B);
}